// round 15
// baseline (speedup 1.0000x reference)
#include <cuda_runtime.h>

#define Bn 8
#define Cn 24
#define Mn 960
#define Wn 15                   // 64-bit words per row (960/64)
#define ROWS (Bn*Mn)            // 7680
#define NW (ROWS*Wn)            // 115200 words
#define TPI 60                  // 16-row tiles per image (960/16)
#define NTILE (ROWS/16)         // 480 tiles

typedef unsigned long long u64;

// Global bitmap planes: frontier + hrode r = 4,6,7,8,9,10 (unpadded, Wn stride).
__device__ u64 g_F[NW];
__device__ u64 g_P[6][NW];
// Handshake flags (zero-init; each slot reset by its single consumer).
__device__ int g_flag0[NTILE];  // set by tile i, consumed by tile i+1
__device__ int g_flag1[NTILE];  // set by tile i, consumed by tile i-1

// in-tile terms from smem, boundary terms from global
#define TERM(dy, p) do {                                                 \
    int ry = rr - 1 + (dy);                                              \
    u64 v;                                                               \
    if ((unsigned)ry < 16u) v = sP[p][ry][w];                            \
    else v = g_P[p][(size_t)(b * Mn + y + (dy)) * Wn + w];               \
    e &= v; } while (0)
#define TERMF(dy) do {                                                   \
    int ry = rr - 1 + (dy);                                              \
    u64 v;                                                               \
    if ((unsigned)ry < 16u) v = sF[ry][w];                               \
    else v = g_F[(size_t)(b * Mn + y + (dy)) * Wn + w];                  \
    e &= v; } while (0)

__global__ void __launch_bounds__(256) fused_kernel(const float* __restrict__ in,
                                                    float* __restrict__ out) {
    __shared__ u64 sF[16][Wn];
    __shared__ u64 sP[6][16][Wn];                     // in-tile hrode planes
    __shared__ u64 sE[18][16];                        // eroded rows (±1), word 15 = 0
    __shared__ u64 sB[16][Wn];
    __shared__ float4 lut[16];

    const int t    = threadIdx.x;
    const int lane = t & 31;
    const int warp = t >> 5;
    const int tile = blockIdx.x;
    const int ii   = tile % TPI;                      // tile index within image
    const int row0 = tile * 16;                       // global row = b*Mn + y
    const int b    = row0 / Mn;
    const int y0   = row0 - b * Mn;

    if (t < 16)
        lut[t] = make_float4(t & 1 ? 1.0f : 0.0f, t & 2 ? 1.0f : 0.0f,
                             t & 4 ? 1.0f : 0.0f, t & 8 ? 1.0f : 0.0f);

    // ── pack: ballot 16 rows (8 warps x 2 rows)
#pragma unroll
    for (int i = 0; i < 2; i++) {
        int rr = warp + (i << 3);
        int y = y0 + rr;
        const float* p = in + ((size_t)(b * Cn + 1) * Mn + y) * Mn + lane;
        float v[30];
#pragma unroll
        for (int j = 0; j < 30; j++) v[j] = p[j * 32];
        unsigned bb[30];
#pragma unroll
        for (int j = 0; j < 30; j++) bb[j] = __ballot_sync(0xffffffffu, v[j] == 0.0f);
        if (lane < Wn) {
            unsigned lo = 0, hi = 0;
#pragma unroll
            for (int k = 0; k < Wn; k++)
                if (lane == k) { lo = bb[2 * k]; hi = bb[2 * k + 1]; }
            sF[rr][lane] = ((u64)hi << 32) | lo;
        }
    }
    __syncthreads();

    // ── hrode: 240 tasks; planes to smem + global (neighbors read global)
    if (t < 16 * Wn) {
        int rr = t / Wn, w = t - rr * Wn;
        u64 c = sF[rr][w];
        u64 l = (w > 0)      ? sF[rr][w - 1] : 0ULL;
        u64 r = (w < Wn - 1) ? sF[rr][w + 1] : 0ULL;
        int i = (row0 + rr) * Wn + w;
        g_F[i] = c;
        u64 acc = c;
#pragma unroll
        for (int d = 1; d <= 10; d++) {
            acc &= ((c << d) | (l >> (64 - d))) & ((c >> d) | (r << (64 - d)));
            if (d == 4)       { sP[0][rr][w] = acc; g_P[0][i] = acc; }
            else if (d == 6)  { sP[1][rr][w] = acc; g_P[1][i] = acc; }
            else if (d == 7)  { sP[2][rr][w] = acc; g_P[2][i] = acc; }
            else if (d == 8)  { sP[3][rr][w] = acc; g_P[3][i] = acc; }
            else if (d == 9)  { sP[4][rr][w] = acc; g_P[4][i] = acc; }
            else if (d == 10) { sP[5][rr][w] = acc; g_P[5][i] = acc; }
        }
    }
    __syncthreads();

    // ── publish + wait for vertical neighbors (capacity >= grid: no deadlock)
    if (t == 0) {
        __threadfence();
        atomicExch(&g_flag0[tile], 1);
        atomicExch(&g_flag1[tile], 1);
        if (ii > 0)       while (atomicAdd(&g_flag0[tile - 1], 0) == 0) {}
        if (ii < TPI - 1) while (atomicAdd(&g_flag1[tile + 1], 0) == 0) {}
        __threadfence();
    }
    __syncthreads();

    // ── vertical 21-term AND: eroded rows y0-1 .. y0+16 (270 tasks) + zero pads
    if (t < 18) sE[t][15] = 0ULL;
    for (int task = t; task < 18 * Wn; task += 256) {
        int rr = task / Wn, w = task - rr * Wn;
        int y = y0 + rr - 1;
        u64 e = 0ULL;
        if (y >= 10 && y <= Mn - 11) {
            e = ~0ULL;
            TERM(0, 5);                                        // r10
            TERM(-1, 4);  TERM(1, 4);  TERM(-2, 4);  TERM(2, 4);   // r9
            TERM(-3, 4);  TERM(3, 4);  TERM(-4, 4);  TERM(4, 4);
            TERM(-5, 3);  TERM(5, 3);  TERM(-6, 3);  TERM(6, 3);   // r8
            TERM(-7, 2);  TERM(7, 2);                              // r7
            TERM(-8, 1);  TERM(8, 1);                              // r6
            TERM(-9, 0);  TERM(9, 0);                              // r4
            TERMF(-10);   TERMF(10);                               // r0
        }
        sE[rr][w] = e;
    }
    __syncthreads();

    // ── release consumed flags (all neighbor reads complete)
    if (t == 0) {
        if (ii > 0)       atomicExch(&g_flag0[tile - 1], 0);
        if (ii < TPI - 1) atomicExch(&g_flag1[tile + 1], 0);
    }

    // ── border = dilate(e, cross) & ~e (240 tasks)
    if (t < 16 * Wn) {
        int rr = t / Wn, w = t - rr * Wn;
        u64 e  = sE[rr + 1][w];
        u64 eu = sE[rr][w];
        u64 ed = sE[rr + 2][w];
        u64 l  = (w > 0) ? sE[rr + 1][w - 1] : 0ULL;
        u64 r  = sE[rr + 1][w + 1];                   // pad word 0 at w=14
        u64 d = e | eu | ed | (e << 1) | (l >> 63) | (e >> 1) | (r << 63);
        sB[rr][w] = d & ~e;
    }
    __syncthreads();

    // ── expand: 16 rows x 240 float4; row = loop constant, col = t (t<240)
    if (t < 240) {
        const int w  = t >> 4;
        const int sh = (t & 15) << 2;
        float4* o = (float4*)out + (size_t)row0 * 240 + t;
#pragma unroll
        for (int k = 0; k < 16; k++) {
            unsigned nib = (unsigned)(sB[k][w] >> sh) & 15u;
            o[(size_t)k * 240] = lut[nib];
        }
    }
}

extern "C" void kernel_launch(void* const* d_in, const int* in_sizes, int n_in,
                              void* d_out, int out_size) {
    const float* map_features = (const float*)d_in[0];
    float* out = (float*)d_out;
    fused_kernel<<<NTILE, 256>>>(map_features, out);  // 480 blocks, single launch
}

// round 16
// speedup vs baseline: 1.2959x; 1.2959x over previous
#include <cuda_runtime.h>

#define Bn 8
#define Cn 24
#define Mn 960
#define Wn 15                   // 64-bit words per row (960/64)
#define ROWS (Bn*Mn)            // 7680
#define NW (ROWS*Wn)            // 115200 words
#define TR 8                    // rows per tile
#define TPI (Mn/TR)             // 120 tiles per image
#define NTILE (ROWS/TR)         // 960 tiles

typedef unsigned long long u64;

// Global bitmap planes: frontier + hrode r = 4,6,7,8,9,10 (unpadded, Wn stride).
__device__ u64 g_F[NW];
__device__ u64 g_P[6][NW];
// Handshake flags: 4 planes, each slot has exactly ONE consumer (reset by it).
// [0][i] consumed by tile i+1, [1][i] by i+2, [2][i] by i-1, [3][i] by i-2.
__device__ int g_flag[4][NTILE];

__global__ void __launch_bounds__(128, 8) fused_kernel(const float* __restrict__ in,
                                                       float* __restrict__ out) {
    __shared__ u64 sF[TR][Wn];
    __shared__ u64 sE[TR + 2][16];                    // eroded rows (±1), word 15 = 0
    __shared__ u64 sB[TR][Wn];
    __shared__ float4 lut[16];

    const int t    = threadIdx.x;
    const int lane = t & 31;
    const int warp = t >> 5;
    const int tile = blockIdx.x;
    const int ii   = tile % TPI;                      // tile index within image
    const int row0 = tile * TR;                       // global row = b*Mn + y
    const int b    = row0 / Mn;
    const int y0   = row0 - b * Mn;

    if (t < 16)
        lut[t] = make_float4(t & 1 ? 1.0f : 0.0f, t & 2 ? 1.0f : 0.0f,
                             t & 4 ? 1.0f : 0.0f, t & 8 ? 1.0f : 0.0f);

    // ── pack: ballot 8 rows (4 warps x 2 rows)
#pragma unroll
    for (int i = 0; i < 2; i++) {
        int rr = warp * 2 + i;
        int y = y0 + rr;
        const float* p = in + ((size_t)(b * Cn + 1) * Mn + y) * Mn + lane;
        float v[30];
#pragma unroll
        for (int j = 0; j < 30; j++) v[j] = p[j * 32];
        unsigned bb[30];
#pragma unroll
        for (int j = 0; j < 30; j++) bb[j] = __ballot_sync(0xffffffffu, v[j] == 0.0f);
        if (lane < Wn) {
            unsigned lo = 0, hi = 0;
#pragma unroll
            for (int k = 0; k < Wn; k++)
                if (lane == k) { lo = bb[2 * k]; hi = bb[2 * k + 1]; }
            sF[rr][lane] = ((u64)hi << 32) | lo;
        }
    }
    __syncthreads();

    // ── hrode: 120 tasks, planes to global
    if (t < TR * Wn) {
        int rr = t / Wn, w = t - rr * Wn;
        u64 c = sF[rr][w];
        u64 l = (w > 0)      ? sF[rr][w - 1] : 0ULL;
        u64 r = (w < Wn - 1) ? sF[rr][w + 1] : 0ULL;
        int i = (row0 + rr) * Wn + w;
        g_F[i] = c;
        u64 acc = c;
#pragma unroll
        for (int d = 1; d <= 10; d++) {
            acc &= ((c << d) | (l >> (64 - d))) & ((c >> d) | (r << (64 - d)));
            if (d == 4)       g_P[0][i] = acc;
            else if (d == 6)  g_P[1][i] = acc;
            else if (d == 7)  g_P[2][i] = acc;
            else if (d == 8)  g_P[3][i] = acc;
            else if (d == 9)  g_P[4][i] = acc;
            else if (d == 10) g_P[5][i] = acc;
        }
    }
    __syncthreads();

    // ── publish + wait for 4 vertical neighbor tiles (all 960 CTAs co-resident)
    if (t == 0) {
        __threadfence();
        atomicExch(&g_flag[0][tile], 1);
        atomicExch(&g_flag[1][tile], 1);
        atomicExch(&g_flag[2][tile], 1);
        atomicExch(&g_flag[3][tile], 1);
        if (ii >= 1)       while (atomicAdd(&g_flag[0][tile - 1], 0) == 0) {}
        if (ii >= 2)       while (atomicAdd(&g_flag[1][tile - 2], 0) == 0) {}
        if (ii <= TPI - 2) while (atomicAdd(&g_flag[2][tile + 1], 0) == 0) {}
        if (ii <= TPI - 3) while (atomicAdd(&g_flag[3][tile + 2], 0) == 0) {}
        __threadfence();
    }
    __syncthreads();

    // ── vertical 21-term AND: eroded rows y0-1 .. y0+8 (150 tasks) + zero pads
    if (t < TR + 2) sE[t][15] = 0ULL;
    for (int task = t; task < (TR + 2) * Wn; task += 128) {
        int rr = task / Wn, w = task - rr * Wn;
        int y = y0 + rr - 1;
        u64 e = 0ULL;
        if (y >= 10 && y <= Mn - 11) {
            int i = (b * Mn + y) * Wn + w;
            u64 v0  = g_P[5][i];
            u64 v1  = g_P[4][i - 1*Wn];  u64 v2  = g_P[4][i + 1*Wn];
            u64 v3  = g_P[4][i - 2*Wn];  u64 v4  = g_P[4][i + 2*Wn];
            u64 v5  = g_P[4][i - 3*Wn];  u64 v6  = g_P[4][i + 3*Wn];
            u64 v7  = g_P[4][i - 4*Wn];  u64 v8  = g_P[4][i + 4*Wn];
            u64 v9  = g_P[3][i - 5*Wn];  u64 v10 = g_P[3][i + 5*Wn];
            u64 v11 = g_P[3][i - 6*Wn];  u64 v12 = g_P[3][i + 6*Wn];
            u64 v13 = g_P[2][i - 7*Wn];  u64 v14 = g_P[2][i + 7*Wn];
            u64 v15 = g_P[1][i - 8*Wn];  u64 v16 = g_P[1][i + 8*Wn];
            u64 v17 = g_P[0][i - 9*Wn];  u64 v18 = g_P[0][i + 9*Wn];
            u64 v19 = g_F[i - 10*Wn];    u64 v20 = g_F[i + 10*Wn];
            u64 a0 = (v0 & v1) & (v2 & v3);
            u64 a1 = (v4 & v5) & (v6 & v7);
            u64 a2 = (v8 & v9) & (v10 & v11);
            u64 a3 = (v12 & v13) & (v14 & v15);
            u64 a4 = (v16 & v17) & (v18 & v19);
            e = ((a0 & a1) & (a2 & a3)) & (a4 & v20);
        }
        sE[rr][w] = e;
    }
    __syncthreads();

    // ── release the consumed flag slots (exactly one consumer each)
    if (t == 0) {
        if (ii >= 1)       atomicExch(&g_flag[0][tile - 1], 0);
        if (ii >= 2)       atomicExch(&g_flag[1][tile - 2], 0);
        if (ii <= TPI - 2) atomicExch(&g_flag[2][tile + 1], 0);
        if (ii <= TPI - 3) atomicExch(&g_flag[3][tile + 2], 0);
    }

    // ── border = dilate(e, cross) & ~e (120 tasks)
    if (t < TR * Wn) {
        int rr = t / Wn, w = t - rr * Wn;
        u64 e  = sE[rr + 1][w];
        u64 eu = sE[rr][w];
        u64 ed = sE[rr + 2][w];
        u64 l  = (w > 0) ? sE[rr + 1][w - 1] : 0ULL;
        u64 r  = sE[rr + 1][w + 1];                   // pad word 0 at w=14
        u64 d = e | eu | ed | (e << 1) | (l >> 63) | (e >> 1) | (r << 63);
        sB[rr][w] = d & ~e;
    }
    __syncthreads();

    // ── expand: 8 rows x 240 float4 = 1920 chunks, 15/thread, coalesced
    float4* o = (float4*)out + (size_t)row0 * 240;
#pragma unroll
    for (int k = 0; k < 15; k++) {
        int c = k * 128 + t;                          // 0..1919 == rr*240+cc
        int rr = c / 240, cc = c - rr * 240;
        unsigned nib = (unsigned)(sB[rr][cc >> 4] >> ((cc & 15) << 2)) & 15u;
        o[c] = lut[nib];
    }
}

extern "C" void kernel_launch(void* const* d_in, const int* in_sizes, int n_in,
                              void* d_out, int out_size) {
    const float* map_features = (const float*)d_in[0];
    float* out = (float*)d_out;
    fused_kernel<<<NTILE, 128>>>(map_features, out);  // 960 blocks, single launch
}